// round 8
// baseline (speedup 1.0000x reference)
#include <cuda_runtime.h>
#include <cuda_bf16.h>
#include <cstdint>

#define BATCH 8
#define SEQ   2048
#define DIM   512
#define TOK   (BATCH*SEQ)          // 16384

typedef __nv_bfloat16 bf16;

// ---------------------------------------------------------------------------
// Scratch (__device__ globals: allocation-guard safe)
// ---------------------------------------------------------------------------
__device__ bf16  g_Xh[(size_t)TOK * DIM],  g_Xl[(size_t)TOK * DIM];
__device__ bf16  g_WTh[3][DIM * DIM],      g_WTl[3][DIM * DIM];   // W^T hi/lo
__device__ bf16  g_QKh[2][(size_t)TOK * DIM], g_QKl[2][(size_t)TOK * DIM]; // Q=0, K=1
__device__ bf16  g_Vth[(size_t)DIM * TOK], g_Vtl[(size_t)DIM * TOK]; // V^T [512,16384]
__device__ float g_P [(size_t)BATCH * SEQ * SEQ];
__device__ bf16  g_Ph[(size_t)BATCH * SEQ * SEQ], g_Pl[(size_t)BATCH * SEQ * SEQ];

// ---------------------------------------------------------------------------
// Baseline-PTX helpers (sm_80+: valid for compute_103 target)
// ---------------------------------------------------------------------------
__device__ __forceinline__ uint32_t s2u(const void* p) {
    uint32_t a;
    asm("{ .reg .u64 t; cvta.to.shared.u64 t, %1; cvt.u32.u64 %0, t; }" : "=r"(a) : "l"(p));
    return a;
}
__device__ __forceinline__ void cp16(uint32_t saddr, const bf16* g) {
    asm volatile("cp.async.cg.shared.global [%0], [%1], 16;"
                 :: "r"(saddr), "l"(__cvta_generic_to_global(g)) : "memory");
}
__device__ __forceinline__ void cp_commit() {
    asm volatile("cp.async.commit_group;" ::: "memory");
}
template <int N>
__device__ __forceinline__ void cp_wait() {
    asm volatile("cp.async.wait_group %0;" :: "n"(N) : "memory");
}
__device__ __forceinline__ void ldsm4(uint32_t* d, uint32_t a) {
    asm volatile("ldmatrix.sync.aligned.m8n8.x4.shared.b16 {%0,%1,%2,%3}, [%4];"
                 : "=r"(d[0]), "=r"(d[1]), "=r"(d[2]), "=r"(d[3]) : "r"(a));
}
__device__ __forceinline__ void mma16816(float* c, const uint32_t* a, const uint32_t* b) {
    asm volatile("mma.sync.aligned.m16n8k16.row.col.f32.bf16.bf16.f32 "
                 "{%0,%1,%2,%3}, {%4,%5,%6,%7}, {%8,%9}, {%0,%1,%2,%3};"
                 : "+f"(c[0]), "+f"(c[1]), "+f"(c[2]), "+f"(c[3])
                 : "r"(a[0]), "r"(a[1]), "r"(a[2]), "r"(a[3]), "r"(b[0]), "r"(b[1]));
}
__device__ __forceinline__ void split2(float v, bf16& h, bf16& l) {
    h = __float2bfloat16(v);
    l = __float2bfloat16(v - __bfloat162float(h));
}

// ---------------------------------------------------------------------------
// HMMA hi/lo GEMM: C[M,N] = Ah·Bh^T + Ah·Bl^T + Al·Bh^T  (all operands K-major)
// CTA 128x128, BK=32, 256 threads (8 warps 4x2, warp tile 32x64), 3-stage
// cp.async pipeline, 2 CTAs/SM, prefetch issued BEFORE compute.
// EPI=0: fp32 C. EPI=1: bf16 hi/lo Ch/Cl.  grid = (N/128, M/128, batch)
// ---------------------------------------------------------------------------
#define STAGE_BYTES 32768          // 4 tiles x 8KB (Ah, Al, Bh, Bl), 128 rows x 64B
#define NSTAGE      3
#define SMEM_BYTES  (NSTAGE * STAGE_BYTES)

template <int EPI>
__global__ __launch_bounds__(256, 2)
void gemm_mma(const bf16* __restrict__ Ah, const bf16* __restrict__ Al, int lda, size_t sA,
              const bf16* __restrict__ Bh, const bf16* __restrict__ Bl, int ldb, size_t sB,
              float* __restrict__ C, bf16* __restrict__ Ch, bf16* __restrict__ Cl,
              int ldc, size_t sC, int Kd)
{
    extern __shared__ __align__(1024) char smem[];
    const uint32_t sbase = s2u(smem);

    const int tid  = threadIdx.x;
    const int lane = tid & 31;
    const int wid  = tid >> 5;
    const int wm   = wid >> 1;        // 0..3 -> m offset wm*32
    const int wn   = wid & 1;         // 0..1 -> n offset wn*64

    Ah += (size_t)blockIdx.z * sA;  Al += (size_t)blockIdx.z * sA;
    Bh += (size_t)blockIdx.z * sB;  Bl += (size_t)blockIdx.z * sB;
    if (C)  C  += (size_t)blockIdx.z * sC;
    if (Ch) Ch += (size_t)blockIdx.z * sC;
    if (Cl) Cl += (size_t)blockIdx.z * sC;
    const size_t bm = (size_t)blockIdx.y * 128;
    const size_t bn = (size_t)blockIdx.x * 128;

    const int nch = Kd >> 5;          // chunks of 32

    // gmem->smem copy: per tile 512 chunks of 16B; thread handles rows r0, r0+64
    // at chunk ch.  Swizzle: xch = ch ^ ((row>>1)&3); (row+64) keeps same xch.
    const int cr0 = tid >> 2;          // 0..63
    const int cch = tid & 3;
    const uint32_t s0 = (uint32_t)cr0 * 64 + (uint32_t)((cch ^ ((cr0 >> 1) & 3)) << 4);

    auto load_stage = [&](int stage, int c) {
        const uint32_t so = sbase + (uint32_t)stage * STAGE_BYTES;
        const size_t ka = (size_t)(c << 5) + cch * 8;
        const bf16* a_h = Ah + (bm + cr0) * (size_t)lda + ka;
        const bf16* a_l = Al + (bm + cr0) * (size_t)lda + ka;
        const bf16* b_h = Bh + (bn + cr0) * (size_t)ldb + ka;
        const bf16* b_l = Bl + (bn + cr0) * (size_t)ldb + ka;
        const size_t r64a = (size_t)64 * lda, r64b = (size_t)64 * ldb;
        cp16(so +          s0,         a_h);
        cp16(so +          s0 + 4096u, a_h + r64a);
        cp16(so +  8192u + s0,         a_l);
        cp16(so +  8192u + s0 + 4096u, a_l + r64a);
        cp16(so + 16384u + s0,         b_h);
        cp16(so + 16384u + s0 + 4096u, b_h + r64b);
        cp16(so + 24576u + s0,         b_l);
        cp16(so + 24576u + s0 + 4096u, b_l + r64b);
        cp_commit();
    };

    // ldmatrix per-lane pieces
    const int lg = lane >> 3, lr = lane & 7;
    const int a_row_off = (lg & 1) * 8 + lr;   // A-op (m-major)
    const int a_ch_off  = lg >> 1;
    const int b_row_off = (lg >> 1) * 8 + lr;  // B-op (n-major)
    const int b_ch_off  = lg & 1;

    uint32_t ahf[2][4], alf[2][4], bhf[4][4], blf[4][4];

    auto frag_load = [&](uint32_t sb, int ks) {
        #pragma unroll
        for (int mt = 0; mt < 2; mt++) {
            const int row = wm * 32 + mt * 16 + a_row_off;
            const int ch  = 2 * ks + a_ch_off;
            const uint32_t off = (uint32_t)row * 64 + (uint32_t)(((ch ^ ((row >> 1) & 3)) & 3) << 4);
            ldsm4(ahf[mt], sb + off);
            ldsm4(alf[mt], sb + 8192u + off);
        }
        #pragma unroll
        for (int p = 0; p < 4; p++) {
            const int row = wn * 64 + p * 16 + b_row_off;
            const int ch  = 2 * ks + b_ch_off;
            const uint32_t off = (uint32_t)row * 64 + (uint32_t)(((ch ^ ((row >> 1) & 3)) & 3) << 4);
            ldsm4(bhf[p], sb + 16384u + off);
            ldsm4(blf[p], sb + 24576u + off);
        }
    };

    float acc[2][8][4];
    #pragma unroll
    for (int mt = 0; mt < 2; mt++)
        #pragma unroll
        for (int nt = 0; nt < 8; nt++)
            #pragma unroll
            for (int q = 0; q < 4; q++) acc[mt][nt][q] = 0.0f;

    auto compute = [&]() {
        #pragma unroll
        for (int mt = 0; mt < 2; mt++)
            #pragma unroll
            for (int p = 0; p < 4; p++) {
                mma16816(acc[mt][2 * p],     ahf[mt], &bhf[p][0]);
                mma16816(acc[mt][2 * p + 1], ahf[mt], &bhf[p][2]);
            }
        #pragma unroll
        for (int mt = 0; mt < 2; mt++)
            #pragma unroll
            for (int p = 0; p < 4; p++) {
                mma16816(acc[mt][2 * p],     ahf[mt], &blf[p][0]);
                mma16816(acc[mt][2 * p + 1], ahf[mt], &blf[p][2]);
            }
        #pragma unroll
        for (int mt = 0; mt < 2; mt++)
            #pragma unroll
            for (int p = 0; p < 4; p++) {
                mma16816(acc[mt][2 * p],     alf[mt], &bhf[p][0]);
                mma16816(acc[mt][2 * p + 1], alf[mt], &bhf[p][2]);
            }
    };

    // 3-stage pipeline prologue: stages 0,1 in flight
    load_stage(0, 0);
    load_stage(1, 1);

    int slot = 0;
    for (int c = 0; c < nch; c++) {
        if (c + 1 < nch) cp_wait<1>(); else cp_wait<0>();
        __syncthreads();

        // R7: issue next-next stage BEFORE compute so its gmem latency overlaps
        // the whole chunk's MMA work. Slot (slot+2)%NSTAGE was freed by the
        // previous iteration's compute (all threads passed it before this sync).
        if (c + 2 < nch) {
            int nslot = slot + 2; if (nslot >= NSTAGE) nslot -= NSTAGE;
            load_stage(nslot, c + 2);
        }

        const uint32_t sb = sbase + (uint32_t)slot * STAGE_BYTES;
        frag_load(sb, 0);
        compute();
        frag_load(sb, 1);
        compute();

        if (++slot == NSTAGE) slot = 0;
    }

    // Epilogue: m16n8k16 acc: c0,c1 -> (r, c),(r, c+1); c2,c3 -> (r+8, ..)
    const int er = lane >> 2, ec = (lane & 3) * 2;
    #pragma unroll
    for (int mt = 0; mt < 2; mt++) {
        const size_t row0 = bm + wm * 32 + mt * 16 + er;
        #pragma unroll
        for (int nt = 0; nt < 8; nt++) {
            const size_t col = bn + wn * 64 + nt * 8 + ec;
            if (EPI == 0) {
                float2 v0 = make_float2(acc[mt][nt][0], acc[mt][nt][1]);
                float2 v1 = make_float2(acc[mt][nt][2], acc[mt][nt][3]);
                *(float2*)&C[row0 * ldc + col]       = v0;
                *(float2*)&C[(row0 + 8) * ldc + col] = v1;
            } else {
                bf16 h0, l0, h1, l1;
                split2(acc[mt][nt][0], h0, l0); split2(acc[mt][nt][1], h1, l1);
                *(__nv_bfloat162*)&Ch[row0 * ldc + col] = __nv_bfloat162(h0, h1);
                *(__nv_bfloat162*)&Cl[row0 * ldc + col] = __nv_bfloat162(l0, l1);
                split2(acc[mt][nt][2], h0, l0); split2(acc[mt][nt][3], h1, l1);
                *(__nv_bfloat162*)&Ch[(row0 + 8) * ldc + col] = __nv_bfloat162(h0, h1);
                *(__nv_bfloat162*)&Cl[(row0 + 8) * ldc + col] = __nv_bfloat162(l0, l1);
            }
        }
    }
}

// ---------------------------------------------------------------------------
// x fp32 -> hi/lo bf16 (elementwise, float4)
// ---------------------------------------------------------------------------
__global__ __launch_bounds__(256)
void convert_split(const float4* __restrict__ in, uint2* __restrict__ oh, uint2* __restrict__ ol)
{
    const size_t i = (size_t)blockIdx.x * 256 + threadIdx.x;
    float4 v = in[i];
    bf16 h[4], l[4];
    split2(v.x, h[0], l[0]); split2(v.y, h[1], l[1]);
    split2(v.z, h[2], l[2]); split2(v.w, h[3], l[3]);
    oh[i] = *(uint2*)h;  ol[i] = *(uint2*)l;
}

// ---------------------------------------------------------------------------
// W [512,512] -> W^T hi/lo bf16 (tiled transpose)
// ---------------------------------------------------------------------------
__global__ __launch_bounds__(256)
void wtrans(const float* __restrict__ W, bf16* __restrict__ Th, bf16* __restrict__ Tl)
{
    __shared__ float t[32][33];
    const int bx = blockIdx.x * 32, by = blockIdx.y * 32;
    const int tx = threadIdx.x, ty = threadIdx.y;
    #pragma unroll
    for (int i = ty; i < 32; i += 8)
        t[i][tx] = W[(size_t)(by + i) * DIM + bx + tx];
    __syncthreads();
    #pragma unroll
    for (int i = ty; i < 32; i += 8) {
        float v = t[tx][i];                               // = W[by+tx][bx+i]
        bf16 h, l; split2(v, h, l);
        Th[(size_t)(bx + i) * DIM + by + tx] = h;         // W^T
        Tl[(size_t)(bx + i) * DIM + by + tx] = l;
    }
}

// ---------------------------------------------------------------------------
// Row softmax of P (fp32) -> hi/lo bf16. One block per row (2048 cols).
// ---------------------------------------------------------------------------
__global__ __launch_bounds__(256)
void softmax_split(const float* __restrict__ P, bf16* __restrict__ Ph, bf16* __restrict__ Pl)
{
    const float* p = P + (size_t)blockIdx.x * SEQ;
    const int tid = threadIdx.x;
    __shared__ float red[8];

    float4 a = *(const float4*)&p[tid * 4];
    float4 b = *(const float4*)&p[1024 + tid * 4];
    float v[8] = {a.x, a.y, a.z, a.w, b.x, b.y, b.z, b.w};

    float m = v[0];
    #pragma unroll
    for (int i = 1; i < 8; i++) m = fmaxf(m, v[i]);
    #pragma unroll
    for (int o = 16; o > 0; o >>= 1) m = fmaxf(m, __shfl_xor_sync(~0u, m, o));
    if ((tid & 31) == 0) red[tid >> 5] = m;
    __syncthreads();
    m = red[0];
    #pragma unroll
    for (int i = 1; i < 8; i++) m = fmaxf(m, red[i]);
    __syncthreads();

    const float sc = 0.044194173824159216f;   // 1/sqrt(512)
    float s = 0.0f;
    #pragma unroll
    for (int i = 0; i < 8; i++) { v[i] = __expf((v[i] - m) * sc); s += v[i]; }
    #pragma unroll
    for (int o = 16; o > 0; o >>= 1) s += __shfl_xor_sync(~0u, s, o);
    if ((tid & 31) == 0) red[tid >> 5] = s;
    __syncthreads();
    s = 0.0f;
    #pragma unroll
    for (int i = 0; i < 8; i++) s += red[i];
    const float rinv = 1.0f / s;

    bf16 h[8], l[8];
    #pragma unroll
    for (int i = 0; i < 8; i++) split2(v[i] * rinv, h[i], l[i]);
    const size_t base = (size_t)blockIdx.x * SEQ;
    *(uint2*)&Ph[base + tid * 4]        = *(uint2*)&h[0];
    *(uint2*)&Ph[base + 1024 + tid * 4] = *(uint2*)&h[4];
    *(uint2*)&Pl[base + tid * 4]        = *(uint2*)&l[0];
    *(uint2*)&Pl[base + 1024 + tid * 4] = *(uint2*)&l[4];
}

// ---------------------------------------------------------------------------
extern "C" void kernel_launch(void* const* d_in, const int* in_sizes, int n_in,
                              void* d_out, int out_size)
{
    const float* x  = (const float*)d_in[0];
    const float* Wq = (const float*)d_in[1];
    const float* Wk = (const float*)d_in[2];
    const float* Wv = (const float*)d_in[3];
    float* out = (float*)d_out;

    bf16 *Xh, *Xl, *WTh, *WTl, *QKh, *QKl, *Vth, *Vtl, *Ph, *Pl;
    float* P;
    cudaGetSymbolAddress((void**)&Xh, g_Xh);   cudaGetSymbolAddress((void**)&Xl, g_Xl);
    cudaGetSymbolAddress((void**)&WTh, g_WTh); cudaGetSymbolAddress((void**)&WTl, g_WTl);
    cudaGetSymbolAddress((void**)&QKh, g_QKh); cudaGetSymbolAddress((void**)&QKl, g_QKl);
    cudaGetSymbolAddress((void**)&Vth, g_Vth); cudaGetSymbolAddress((void**)&Vtl, g_Vtl);
    cudaGetSymbolAddress((void**)&P, g_P);
    cudaGetSymbolAddress((void**)&Ph, g_Ph);   cudaGetSymbolAddress((void**)&Pl, g_Pl);

    const size_t QK = (size_t)TOK * DIM;

    cudaFuncSetAttribute(gemm_mma<0>, cudaFuncAttributeMaxDynamicSharedMemorySize, SMEM_BYTES);
    cudaFuncSetAttribute(gemm_mma<1>, cudaFuncAttributeMaxDynamicSharedMemorySize, SMEM_BYTES);

    // launches 0-3: conversions
    convert_split<<<(TOK * DIM) / 1024, 256>>>((const float4*)x, (uint2*)Xh, (uint2*)Xl);
    wtrans<<<dim3(16, 16), dim3(32, 8)>>>(Wq, WTh + 0 * DIM * DIM, WTl + 0 * DIM * DIM);
    wtrans<<<dim3(16, 16), dim3(32, 8)>>>(Wk, WTh + 1 * DIM * DIM, WTl + 1 * DIM * DIM);
    wtrans<<<dim3(16, 16), dim3(32, 8)>>>(Wv, WTh + 2 * DIM * DIM, WTl + 2 * DIM * DIM);

    // launch 4: Q = X @ Wq
    gemm_mma<1><<<dim3(4, 128, 1), 256, SMEM_BYTES>>>(
        Xh, Xl, DIM, 0, WTh, WTl, DIM, 0,
        nullptr, QKh, QKl, DIM, 0, DIM);
    // launch 5 (ncu -s 5 -c 1 captures THIS): K = X @ Wk  — representative GEMM
    gemm_mma<1><<<dim3(4, 128, 1), 256, SMEM_BYTES>>>(
        Xh, Xl, DIM, 0, WTh + DIM * DIM, WTl + DIM * DIM, DIM, 0,
        nullptr, QKh + QK, QKl + QK, DIM, 0, DIM);
    // launch 6: V^T[e, tok] = sum_d Wv^T[e,d] * X[tok,d]
    gemm_mma<1><<<dim3(128, 4, 1), 256, SMEM_BYTES>>>(
        WTh + 2 * DIM * DIM, WTl + 2 * DIM * DIM, DIM, 0, Xh, Xl, DIM, 0,
        nullptr, Vth, Vtl, TOK, 0, DIM);

    // P[b] = Q[b] @ K[b]^T  (fp32 out)
    gemm_mma<0><<<dim3(16, 16, BATCH), 256, SMEM_BYTES>>>(
        QKh, QKl, DIM, (size_t)SEQ * DIM, QKh + QK, QKl + QK, DIM, (size_t)SEQ * DIM,
        P, nullptr, nullptr, SEQ, (size_t)SEQ * SEQ, DIM);

    // softmax rows + split to bf16 hi/lo
    softmax_split<<<BATCH * SEQ, 256>>>(P, Ph, Pl);

    // out[b] = P[b] @ V[b]  via B = V^T (ldb = TOK, batch column offset)
    gemm_mma<0><<<dim3(4, 16, BATCH), 256, SMEM_BYTES>>>(
        Ph, Pl, SEQ, (size_t)SEQ * SEQ, Vth, Vtl, TOK, (size_t)SEQ,
        out, nullptr, nullptr, DIM, (size_t)SEQ * DIM, SEQ);
}

// round 9
// speedup vs baseline: 1.0363x; 1.0363x over previous
#include <cuda_runtime.h>
#include <cuda_bf16.h>
#include <cstdint>

#define BATCH 8
#define SEQ   2048
#define DIM   512
#define TOK   (BATCH*SEQ)          // 16384

typedef __nv_bfloat16 bf16;

// ---------------------------------------------------------------------------
// Scratch (__device__ globals: allocation-guard safe)
// ---------------------------------------------------------------------------
__device__ bf16  g_Xh[(size_t)TOK * DIM],  g_Xl[(size_t)TOK * DIM];
__device__ bf16  g_WTh[3][DIM * DIM],      g_WTl[3][DIM * DIM];   // W^T hi/lo
__device__ bf16  g_QKh[2][(size_t)TOK * DIM], g_QKl[2][(size_t)TOK * DIM]; // Q=0, K=1
__device__ bf16  g_Vth[(size_t)DIM * TOK], g_Vtl[(size_t)DIM * TOK]; // V^T [512,16384]
// scores (hi/lo bf16) -> probs (hi/lo bf16) in place
__device__ bf16  g_Ph[(size_t)BATCH * SEQ * SEQ], g_Pl[(size_t)BATCH * SEQ * SEQ];

// ---------------------------------------------------------------------------
// Baseline-PTX helpers (sm_80+: valid for compute_103 target)
// ---------------------------------------------------------------------------
__device__ __forceinline__ uint32_t s2u(const void* p) {
    uint32_t a;
    asm("{ .reg .u64 t; cvta.to.shared.u64 t, %1; cvt.u32.u64 %0, t; }" : "=r"(a) : "l"(p));
    return a;
}
__device__ __forceinline__ void cp16(uint32_t saddr, const bf16* g) {
    asm volatile("cp.async.cg.shared.global [%0], [%1], 16;"
                 :: "r"(saddr), "l"(__cvta_generic_to_global(g)) : "memory");
}
__device__ __forceinline__ void cp_commit() {
    asm volatile("cp.async.commit_group;" ::: "memory");
}
template <int N>
__device__ __forceinline__ void cp_wait() {
    asm volatile("cp.async.wait_group %0;" :: "n"(N) : "memory");
}
__device__ __forceinline__ void ldsm4(uint32_t* d, uint32_t a) {
    asm volatile("ldmatrix.sync.aligned.m8n8.x4.shared.b16 {%0,%1,%2,%3}, [%4];"
                 : "=r"(d[0]), "=r"(d[1]), "=r"(d[2]), "=r"(d[3]) : "r"(a));
}
__device__ __forceinline__ void mma16816(float* c, const uint32_t* a, const uint32_t* b) {
    asm volatile("mma.sync.aligned.m16n8k16.row.col.f32.bf16.bf16.f32 "
                 "{%0,%1,%2,%3}, {%4,%5,%6,%7}, {%8,%9}, {%0,%1,%2,%3};"
                 : "+f"(c[0]), "+f"(c[1]), "+f"(c[2]), "+f"(c[3])
                 : "r"(a[0]), "r"(a[1]), "r"(a[2]), "r"(a[3]), "r"(b[0]), "r"(b[1]));
}
__device__ __forceinline__ void split2(float v, bf16& h, bf16& l) {
    h = __float2bfloat16(v);
    l = __float2bfloat16(v - __bfloat162float(h));
}

// ---------------------------------------------------------------------------
// HMMA hi/lo GEMM: C[M,N] = Ah·Bh^T + Ah·Bl^T + Al·Bh^T  (all operands K-major)
// CTA 128x128, BK=32, 256 threads (8 warps 4x2, warp tile 32x64), 3-stage
// cp.async pipeline, 2 CTAs/SM. R6 structure exactly (load_stage AFTER compute).
// EPI=0: fp32 C. EPI=1: bf16 hi/lo Ch/Cl.  grid = (N/128, M/128, batch)
// ---------------------------------------------------------------------------
#define STAGE_BYTES 32768          // 4 tiles x 8KB (Ah, Al, Bh, Bl), 128 rows x 64B
#define NSTAGE      3
#define SMEM_BYTES  (NSTAGE * STAGE_BYTES)

template <int EPI>
__global__ __launch_bounds__(256, 2)
void gemm_mma(const bf16* __restrict__ Ah, const bf16* __restrict__ Al, int lda, size_t sA,
              const bf16* __restrict__ Bh, const bf16* __restrict__ Bl, int ldb, size_t sB,
              float* __restrict__ C, bf16* __restrict__ Ch, bf16* __restrict__ Cl,
              int ldc, size_t sC, int Kd)
{
    extern __shared__ __align__(1024) char smem[];
    const uint32_t sbase = s2u(smem);

    const int tid  = threadIdx.x;
    const int lane = tid & 31;
    const int wid  = tid >> 5;
    const int wm   = wid >> 1;        // 0..3 -> m offset wm*32
    const int wn   = wid & 1;         // 0..1 -> n offset wn*64

    Ah += (size_t)blockIdx.z * sA;  Al += (size_t)blockIdx.z * sA;
    Bh += (size_t)blockIdx.z * sB;  Bl += (size_t)blockIdx.z * sB;
    if (C)  C  += (size_t)blockIdx.z * sC;
    if (Ch) Ch += (size_t)blockIdx.z * sC;
    if (Cl) Cl += (size_t)blockIdx.z * sC;
    const size_t bm = (size_t)blockIdx.y * 128;
    const size_t bn = (size_t)blockIdx.x * 128;

    const int nch = Kd >> 5;          // chunks of 32

    // gmem->smem copy: per tile 512 chunks of 16B; thread handles rows r0, r0+64
    // at chunk ch.  Swizzle: xch = ch ^ ((row>>1)&3); (row+64) keeps same xch.
    const int cr0 = tid >> 2;          // 0..63
    const int cch = tid & 3;
    const uint32_t s0 = (uint32_t)cr0 * 64 + (uint32_t)((cch ^ ((cr0 >> 1) & 3)) << 4);

    auto load_stage = [&](int stage, int c) {
        const uint32_t so = sbase + (uint32_t)stage * STAGE_BYTES;
        const size_t ka = (size_t)(c << 5) + cch * 8;
        const bf16* a_h = Ah + (bm + cr0) * (size_t)lda + ka;
        const bf16* a_l = Al + (bm + cr0) * (size_t)lda + ka;
        const bf16* b_h = Bh + (bn + cr0) * (size_t)ldb + ka;
        const bf16* b_l = Bl + (bn + cr0) * (size_t)ldb + ka;
        const size_t r64a = (size_t)64 * lda, r64b = (size_t)64 * ldb;
        cp16(so +          s0,         a_h);
        cp16(so +          s0 + 4096u, a_h + r64a);
        cp16(so +  8192u + s0,         a_l);
        cp16(so +  8192u + s0 + 4096u, a_l + r64a);
        cp16(so + 16384u + s0,         b_h);
        cp16(so + 16384u + s0 + 4096u, b_h + r64b);
        cp16(so + 24576u + s0,         b_l);
        cp16(so + 24576u + s0 + 4096u, b_l + r64b);
        cp_commit();
    };

    // ldmatrix per-lane pieces
    const int lg = lane >> 3, lr = lane & 7;
    const int a_row_off = (lg & 1) * 8 + lr;   // A-op (m-major)
    const int a_ch_off  = lg >> 1;
    const int b_row_off = (lg >> 1) * 8 + lr;  // B-op (n-major)
    const int b_ch_off  = lg & 1;

    uint32_t ahf[2][4], alf[2][4], bhf[4][4], blf[4][4];

    auto frag_load = [&](uint32_t sb, int ks) {
        #pragma unroll
        for (int mt = 0; mt < 2; mt++) {
            const int row = wm * 32 + mt * 16 + a_row_off;
            const int ch  = 2 * ks + a_ch_off;
            const uint32_t off = (uint32_t)row * 64 + (uint32_t)(((ch ^ ((row >> 1) & 3)) & 3) << 4);
            ldsm4(ahf[mt], sb + off);
            ldsm4(alf[mt], sb + 8192u + off);
        }
        #pragma unroll
        for (int p = 0; p < 4; p++) {
            const int row = wn * 64 + p * 16 + b_row_off;
            const int ch  = 2 * ks + b_ch_off;
            const uint32_t off = (uint32_t)row * 64 + (uint32_t)(((ch ^ ((row >> 1) & 3)) & 3) << 4);
            ldsm4(bhf[p], sb + 16384u + off);
            ldsm4(blf[p], sb + 24576u + off);
        }
    };

    float acc[2][8][4];
    #pragma unroll
    for (int mt = 0; mt < 2; mt++)
        #pragma unroll
        for (int nt = 0; nt < 8; nt++)
            #pragma unroll
            for (int q = 0; q < 4; q++) acc[mt][nt][q] = 0.0f;

    auto compute = [&]() {
        #pragma unroll
        for (int mt = 0; mt < 2; mt++)
            #pragma unroll
            for (int p = 0; p < 4; p++) {
                mma16816(acc[mt][2 * p],     ahf[mt], &bhf[p][0]);
                mma16816(acc[mt][2 * p + 1], ahf[mt], &bhf[p][2]);
            }
        #pragma unroll
        for (int mt = 0; mt < 2; mt++)
            #pragma unroll
            for (int p = 0; p < 4; p++) {
                mma16816(acc[mt][2 * p],     ahf[mt], &blf[p][0]);
                mma16816(acc[mt][2 * p + 1], ahf[mt], &blf[p][2]);
            }
        #pragma unroll
        for (int mt = 0; mt < 2; mt++)
            #pragma unroll
            for (int p = 0; p < 4; p++) {
                mma16816(acc[mt][2 * p],     alf[mt], &bhf[p][0]);
                mma16816(acc[mt][2 * p + 1], alf[mt], &bhf[p][2]);
            }
    };

    // 3-stage pipeline prologue: stages 0,1 in flight
    load_stage(0, 0);
    load_stage(1, 1);

    int slot = 0;
    for (int c = 0; c < nch; c++) {
        if (c + 1 < nch) cp_wait<1>(); else cp_wait<0>();
        __syncthreads();

        const uint32_t sb = sbase + (uint32_t)slot * STAGE_BYTES;
        frag_load(sb, 0);
        compute();
        frag_load(sb, 1);
        compute();

        if (c + 2 < nch) {
            int nslot = slot + 2; if (nslot >= NSTAGE) nslot -= NSTAGE;
            load_stage(nslot, c + 2);
        }
        if (++slot == NSTAGE) slot = 0;
    }

    // Epilogue: m16n8k16 acc: c0,c1 -> (r, c),(r, c+1); c2,c3 -> (r+8, ..)
    const int er = lane >> 2, ec = (lane & 3) * 2;
    #pragma unroll
    for (int mt = 0; mt < 2; mt++) {
        const size_t row0 = bm + wm * 32 + mt * 16 + er;
        #pragma unroll
        for (int nt = 0; nt < 8; nt++) {
            const size_t col = bn + wn * 64 + nt * 8 + ec;
            if (EPI == 0) {
                float2 v0 = make_float2(acc[mt][nt][0], acc[mt][nt][1]);
                float2 v1 = make_float2(acc[mt][nt][2], acc[mt][nt][3]);
                *(float2*)&C[row0 * ldc + col]       = v0;
                *(float2*)&C[(row0 + 8) * ldc + col] = v1;
            } else {
                bf16 h0, l0, h1, l1;
                split2(acc[mt][nt][0], h0, l0); split2(acc[mt][nt][1], h1, l1);
                *(__nv_bfloat162*)&Ch[row0 * ldc + col] = __nv_bfloat162(h0, h1);
                *(__nv_bfloat162*)&Cl[row0 * ldc + col] = __nv_bfloat162(l0, l1);
                split2(acc[mt][nt][2], h0, l0); split2(acc[mt][nt][3], h1, l1);
                *(__nv_bfloat162*)&Ch[(row0 + 8) * ldc + col] = __nv_bfloat162(h0, h1);
                *(__nv_bfloat162*)&Cl[(row0 + 8) * ldc + col] = __nv_bfloat162(l0, l1);
            }
        }
    }
}

// ---------------------------------------------------------------------------
// x fp32 -> hi/lo bf16 (elementwise, float4)
// ---------------------------------------------------------------------------
__global__ __launch_bounds__(256)
void convert_split(const float4* __restrict__ in, uint2* __restrict__ oh, uint2* __restrict__ ol)
{
    const size_t i = (size_t)blockIdx.x * 256 + threadIdx.x;
    float4 v = in[i];
    bf16 h[4], l[4];
    split2(v.x, h[0], l[0]); split2(v.y, h[1], l[1]);
    split2(v.z, h[2], l[2]); split2(v.w, h[3], l[3]);
    oh[i] = *(uint2*)h;  ol[i] = *(uint2*)l;
}

// ---------------------------------------------------------------------------
// W [512,512] -> W^T hi/lo bf16 (tiled transpose)
// ---------------------------------------------------------------------------
__global__ __launch_bounds__(256)
void wtrans(const float* __restrict__ W, bf16* __restrict__ Th, bf16* __restrict__ Tl)
{
    __shared__ float t[32][33];
    const int bx = blockIdx.x * 32, by = blockIdx.y * 32;
    const int tx = threadIdx.x, ty = threadIdx.y;
    #pragma unroll
    for (int i = ty; i < 32; i += 8)
        t[i][tx] = W[(size_t)(by + i) * DIM + bx + tx];
    __syncthreads();
    #pragma unroll
    for (int i = ty; i < 32; i += 8) {
        float v = t[tx][i];                               // = W[by+tx][bx+i]
        bf16 h, l; split2(v, h, l);
        Th[(size_t)(bx + i) * DIM + by + tx] = h;         // W^T
        Tl[(size_t)(bx + i) * DIM + by + tx] = l;
    }
}

// ---------------------------------------------------------------------------
// Row softmax: reads score hi/lo bf16, reconstructs fp32, writes prob hi/lo
// bf16 IN PLACE. One block (256 threads) per row of 2048.
// ---------------------------------------------------------------------------
__global__ __launch_bounds__(256)
void softmax_split(bf16* __restrict__ Ph, bf16* __restrict__ Pl)
{
    const size_t base = (size_t)blockIdx.x * SEQ;
    const int tid = threadIdx.x;
    __shared__ float red[8];

    // load 8 scores (hi + lo)
    uint2 h0 = *(uint2*)&Ph[base + tid * 4];
    uint2 h1 = *(uint2*)&Ph[base + 1024 + tid * 4];
    uint2 l0 = *(uint2*)&Pl[base + tid * 4];
    uint2 l1 = *(uint2*)&Pl[base + 1024 + tid * 4];
    float v[8];
    {
        const bf16* hp0 = (const bf16*)&h0; const bf16* lp0 = (const bf16*)&l0;
        const bf16* hp1 = (const bf16*)&h1; const bf16* lp1 = (const bf16*)&l1;
        #pragma unroll
        for (int i = 0; i < 4; i++) {
            v[i]     = __bfloat162float(hp0[i]) + __bfloat162float(lp0[i]);
            v[4 + i] = __bfloat162float(hp1[i]) + __bfloat162float(lp1[i]);
        }
    }

    float m = v[0];
    #pragma unroll
    for (int i = 1; i < 8; i++) m = fmaxf(m, v[i]);
    #pragma unroll
    for (int o = 16; o > 0; o >>= 1) m = fmaxf(m, __shfl_xor_sync(~0u, m, o));
    if ((tid & 31) == 0) red[tid >> 5] = m;
    __syncthreads();
    m = red[0];
    #pragma unroll
    for (int i = 1; i < 8; i++) m = fmaxf(m, red[i]);
    __syncthreads();

    const float sc = 0.044194173824159216f;   // 1/sqrt(512)
    float s = 0.0f;
    #pragma unroll
    for (int i = 0; i < 8; i++) { v[i] = __expf((v[i] - m) * sc); s += v[i]; }
    #pragma unroll
    for (int o = 16; o > 0; o >>= 1) s += __shfl_xor_sync(~0u, s, o);
    if ((tid & 31) == 0) red[tid >> 5] = s;
    __syncthreads();
    s = 0.0f;
    #pragma unroll
    for (int i = 0; i < 8; i++) s += red[i];
    const float rinv = 1.0f / s;

    bf16 h[8], l[8];
    #pragma unroll
    for (int i = 0; i < 8; i++) split2(v[i] * rinv, h[i], l[i]);
    *(uint2*)&Ph[base + tid * 4]        = *(uint2*)&h[0];
    *(uint2*)&Ph[base + 1024 + tid * 4] = *(uint2*)&h[4];
    *(uint2*)&Pl[base + tid * 4]        = *(uint2*)&l[0];
    *(uint2*)&Pl[base + 1024 + tid * 4] = *(uint2*)&l[4];
}

// ---------------------------------------------------------------------------
extern "C" void kernel_launch(void* const* d_in, const int* in_sizes, int n_in,
                              void* d_out, int out_size)
{
    const float* x  = (const float*)d_in[0];
    const float* Wq = (const float*)d_in[1];
    const float* Wk = (const float*)d_in[2];
    const float* Wv = (const float*)d_in[3];
    float* out = (float*)d_out;

    bf16 *Xh, *Xl, *WTh, *WTl, *QKh, *QKl, *Vth, *Vtl, *Ph, *Pl;
    cudaGetSymbolAddress((void**)&Xh, g_Xh);   cudaGetSymbolAddress((void**)&Xl, g_Xl);
    cudaGetSymbolAddress((void**)&WTh, g_WTh); cudaGetSymbolAddress((void**)&WTl, g_WTl);
    cudaGetSymbolAddress((void**)&QKh, g_QKh); cudaGetSymbolAddress((void**)&QKl, g_QKl);
    cudaGetSymbolAddress((void**)&Vth, g_Vth); cudaGetSymbolAddress((void**)&Vtl, g_Vtl);
    cudaGetSymbolAddress((void**)&Ph, g_Ph);   cudaGetSymbolAddress((void**)&Pl, g_Pl);

    const size_t QK = (size_t)TOK * DIM;

    cudaFuncSetAttribute(gemm_mma<0>, cudaFuncAttributeMaxDynamicSharedMemorySize, SMEM_BYTES);
    cudaFuncSetAttribute(gemm_mma<1>, cudaFuncAttributeMaxDynamicSharedMemorySize, SMEM_BYTES);

    // hi/lo conversions
    convert_split<<<(TOK * DIM) / 1024, 256>>>((const float4*)x, (uint2*)Xh, (uint2*)Xl);
    wtrans<<<dim3(16, 16), dim3(32, 8)>>>(Wq, WTh + 0 * DIM * DIM, WTl + 0 * DIM * DIM);
    wtrans<<<dim3(16, 16), dim3(32, 8)>>>(Wk, WTh + 1 * DIM * DIM, WTl + 1 * DIM * DIM);
    wtrans<<<dim3(16, 16), dim3(32, 8)>>>(Wv, WTh + 2 * DIM * DIM, WTl + 2 * DIM * DIM);

    // Q and K projections in ONE launch: z=0 -> Q (Wq), z=1 -> K (Wk)  [R6]
    gemm_mma<1><<<dim3(4, 128, 2), 256, SMEM_BYTES>>>(
        Xh, Xl, DIM, 0, WTh, WTl, DIM, (size_t)DIM * DIM,
        nullptr, QKh, QKl, DIM, QK, DIM);
    // V^T[e, tok] = sum_d Wv^T[e,d] * X[tok,d]
    gemm_mma<1><<<dim3(128, 4, 1), 256, SMEM_BYTES>>>(
        WTh + 2 * DIM * DIM, WTl + 2 * DIM * DIM, DIM, 0, Xh, Xl, DIM, 0,
        nullptr, Vth, Vtl, TOK, 0, DIM);

    // Scores S[b] = Q[b] @ K[b]^T  -> bf16 hi/lo directly (saves fp32 P traffic)
    gemm_mma<1><<<dim3(16, 16, BATCH), 256, SMEM_BYTES>>>(
        QKh, QKl, DIM, (size_t)SEQ * DIM, QKh + QK, QKl + QK, DIM, (size_t)SEQ * DIM,
        nullptr, Ph, Pl, SEQ, (size_t)SEQ * SEQ, DIM);

    // softmax rows: hi/lo scores -> hi/lo probs, in place
    softmax_split<<<BATCH * SEQ, 256>>>(Ph, Pl);

    // out[b] = P[b] @ V[b]  via B = V^T (ldb = TOK, batch column offset)
    gemm_mma<0><<<dim3(4, 16, BATCH), 256, SMEM_BYTES>>>(
        Ph, Pl, SEQ, (size_t)SEQ * SEQ, Vth, Vtl, TOK, (size_t)SEQ,
        out, nullptr, nullptr, DIM, (size_t)SEQ * DIM, SEQ);
}

// round 10
// speedup vs baseline: 1.0777x; 1.0400x over previous
#include <cuda_runtime.h>
#include <cuda_bf16.h>
#include <cstdint>

#define BATCH 8
#define SEQ   2048
#define DIM   512
#define TOK   (BATCH*SEQ)          // 16384

typedef __nv_bfloat16 bf16;

// ---------------------------------------------------------------------------
// Scratch (__device__ globals: allocation-guard safe)
// ---------------------------------------------------------------------------
__device__ bf16  g_Xh[(size_t)TOK * DIM],  g_Xl[(size_t)TOK * DIM];
__device__ bf16  g_WTh[3][DIM * DIM],      g_WTl[3][DIM * DIM];   // W^T hi/lo
__device__ bf16  g_QKh[2][(size_t)TOK * DIM], g_QKl[2][(size_t)TOK * DIM]; // Q=0, K=1
__device__ bf16  g_Vth[(size_t)DIM * TOK], g_Vtl[(size_t)DIM * TOK]; // V^T [512,16384]
__device__ float g_P [(size_t)BATCH * SEQ * SEQ];
__device__ bf16  g_Ph[(size_t)BATCH * SEQ * SEQ], g_Pl[(size_t)BATCH * SEQ * SEQ];

// ---------------------------------------------------------------------------
// Baseline-PTX helpers (sm_80+: valid for compute_103 target)
// ---------------------------------------------------------------------------
__device__ __forceinline__ uint32_t s2u(const void* p) {
    uint32_t a;
    asm("{ .reg .u64 t; cvta.to.shared.u64 t, %1; cvt.u32.u64 %0, t; }" : "=r"(a) : "l"(p));
    return a;
}
__device__ __forceinline__ void cp16(uint32_t saddr, const bf16* g) {
    asm volatile("cp.async.cg.shared.global [%0], [%1], 16;"
                 :: "r"(saddr), "l"(__cvta_generic_to_global(g)) : "memory");
}
__device__ __forceinline__ void cp_commit() {
    asm volatile("cp.async.commit_group;" ::: "memory");
}
template <int N>
__device__ __forceinline__ void cp_wait() {
    asm volatile("cp.async.wait_group %0;" :: "n"(N) : "memory");
}
__device__ __forceinline__ void ldsm4(uint32_t* d, uint32_t a) {
    asm volatile("ldmatrix.sync.aligned.m8n8.x4.shared.b16 {%0,%1,%2,%3}, [%4];"
                 : "=r"(d[0]), "=r"(d[1]), "=r"(d[2]), "=r"(d[3]) : "r"(a));
}
__device__ __forceinline__ void mma16816(float* c, const uint32_t* a, const uint32_t* b) {
    asm volatile("mma.sync.aligned.m16n8k16.row.col.f32.bf16.bf16.f32 "
                 "{%0,%1,%2,%3}, {%4,%5,%6,%7}, {%8,%9}, {%0,%1,%2,%3};"
                 : "+f"(c[0]), "+f"(c[1]), "+f"(c[2]), "+f"(c[3])
                 : "r"(a[0]), "r"(a[1]), "r"(a[2]), "r"(a[3]), "r"(b[0]), "r"(b[1]));
}
__device__ __forceinline__ void split2(float v, bf16& h, bf16& l) {
    h = __float2bfloat16(v);
    l = __float2bfloat16(v - __bfloat162float(h));
}

// ---------------------------------------------------------------------------
// HMMA hi/lo GEMM: C[M,N] = Ah·Bh^T + Ah·Bl^T + Al·Bh^T  (all operands K-major)
// CTA 128x128, BK=32, 256 threads (8 warps 4x2, warp tile 32x64), 3-stage
// cp.async pipeline, 2 CTAs/SM. R6 structure EXACTLY (load_stage AFTER compute).
// EPI=0: fp32 C. EPI=1: bf16 hi/lo Ch/Cl.  grid = (N/128, M/128, batch)
// ---------------------------------------------------------------------------
#define STAGE_BYTES 32768          // 4 tiles x 8KB (Ah, Al, Bh, Bl), 128 rows x 64B
#define NSTAGE      3
#define SMEM_BYTES  (NSTAGE * STAGE_BYTES)

template <int EPI>
__global__ __launch_bounds__(256, 2)
void gemm_mma(const bf16* __restrict__ Ah, const bf16* __restrict__ Al, int lda, size_t sA,
              const bf16* __restrict__ Bh, const bf16* __restrict__ Bl, int ldb, size_t sB,
              float* __restrict__ C, bf16* __restrict__ Ch, bf16* __restrict__ Cl,
              int ldc, size_t sC, int Kd)
{
    extern __shared__ __align__(1024) char smem[];
    const uint32_t sbase = s2u(smem);

    const int tid  = threadIdx.x;
    const int lane = tid & 31;
    const int wid  = tid >> 5;
    const int wm   = wid >> 1;        // 0..3 -> m offset wm*32
    const int wn   = wid & 1;         // 0..1 -> n offset wn*64

    Ah += (size_t)blockIdx.z * sA;  Al += (size_t)blockIdx.z * sA;
    Bh += (size_t)blockIdx.z * sB;  Bl += (size_t)blockIdx.z * sB;
    if (C)  C  += (size_t)blockIdx.z * sC;
    if (Ch) Ch += (size_t)blockIdx.z * sC;
    if (Cl) Cl += (size_t)blockIdx.z * sC;
    const size_t bm = (size_t)blockIdx.y * 128;
    const size_t bn = (size_t)blockIdx.x * 128;

    const int nch = Kd >> 5;          // chunks of 32

    // gmem->smem copy: per tile 512 chunks of 16B; thread handles rows r0, r0+64
    // at chunk ch.  Swizzle: xch = ch ^ ((row>>1)&3); (row+64) keeps same xch.
    const int cr0 = tid >> 2;          // 0..63
    const int cch = tid & 3;
    const uint32_t s0 = (uint32_t)cr0 * 64 + (uint32_t)((cch ^ ((cr0 >> 1) & 3)) << 4);

    auto load_stage = [&](int stage, int c) {
        const uint32_t so = sbase + (uint32_t)stage * STAGE_BYTES;
        const size_t ka = (size_t)(c << 5) + cch * 8;
        const bf16* a_h = Ah + (bm + cr0) * (size_t)lda + ka;
        const bf16* a_l = Al + (bm + cr0) * (size_t)lda + ka;
        const bf16* b_h = Bh + (bn + cr0) * (size_t)ldb + ka;
        const bf16* b_l = Bl + (bn + cr0) * (size_t)ldb + ka;
        const size_t r64a = (size_t)64 * lda, r64b = (size_t)64 * ldb;
        cp16(so +          s0,         a_h);
        cp16(so +          s0 + 4096u, a_h + r64a);
        cp16(so +  8192u + s0,         a_l);
        cp16(so +  8192u + s0 + 4096u, a_l + r64a);
        cp16(so + 16384u + s0,         b_h);
        cp16(so + 16384u + s0 + 4096u, b_h + r64b);
        cp16(so + 24576u + s0,         b_l);
        cp16(so + 24576u + s0 + 4096u, b_l + r64b);
        cp_commit();
    };

    // ldmatrix per-lane pieces
    const int lg = lane >> 3, lr = lane & 7;
    const int a_row_off = (lg & 1) * 8 + lr;   // A-op (m-major)
    const int a_ch_off  = lg >> 1;
    const int b_row_off = (lg >> 1) * 8 + lr;  // B-op (n-major)
    const int b_ch_off  = lg & 1;

    uint32_t ahf[2][4], alf[2][4], bhf[4][4], blf[4][4];

    auto frag_load = [&](uint32_t sb, int ks) {
        #pragma unroll
        for (int mt = 0; mt < 2; mt++) {
            const int row = wm * 32 + mt * 16 + a_row_off;
            const int ch  = 2 * ks + a_ch_off;
            const uint32_t off = (uint32_t)row * 64 + (uint32_t)(((ch ^ ((row >> 1) & 3)) & 3) << 4);
            ldsm4(ahf[mt], sb + off);
            ldsm4(alf[mt], sb + 8192u + off);
        }
        #pragma unroll
        for (int p = 0; p < 4; p++) {
            const int row = wn * 64 + p * 16 + b_row_off;
            const int ch  = 2 * ks + b_ch_off;
            const uint32_t off = (uint32_t)row * 64 + (uint32_t)(((ch ^ ((row >> 1) & 3)) & 3) << 4);
            ldsm4(bhf[p], sb + 16384u + off);
            ldsm4(blf[p], sb + 24576u + off);
        }
    };

    float acc[2][8][4];
    #pragma unroll
    for (int mt = 0; mt < 2; mt++)
        #pragma unroll
        for (int nt = 0; nt < 8; nt++)
            #pragma unroll
            for (int q = 0; q < 4; q++) acc[mt][nt][q] = 0.0f;

    auto compute = [&]() {
        #pragma unroll
        for (int mt = 0; mt < 2; mt++)
            #pragma unroll
            for (int p = 0; p < 4; p++) {
                mma16816(acc[mt][2 * p],     ahf[mt], &bhf[p][0]);
                mma16816(acc[mt][2 * p + 1], ahf[mt], &bhf[p][2]);
            }
        #pragma unroll
        for (int mt = 0; mt < 2; mt++)
            #pragma unroll
            for (int p = 0; p < 4; p++) {
                mma16816(acc[mt][2 * p],     ahf[mt], &blf[p][0]);
                mma16816(acc[mt][2 * p + 1], ahf[mt], &blf[p][2]);
            }
        #pragma unroll
        for (int mt = 0; mt < 2; mt++)
            #pragma unroll
            for (int p = 0; p < 4; p++) {
                mma16816(acc[mt][2 * p],     alf[mt], &bhf[p][0]);
                mma16816(acc[mt][2 * p + 1], alf[mt], &bhf[p][2]);
            }
    };

    // 3-stage pipeline prologue: stages 0,1 in flight
    load_stage(0, 0);
    load_stage(1, 1);

    int slot = 0;
    for (int c = 0; c < nch; c++) {
        if (c + 1 < nch) cp_wait<1>(); else cp_wait<0>();
        __syncthreads();

        const uint32_t sb = sbase + (uint32_t)slot * STAGE_BYTES;
        frag_load(sb, 0);
        compute();
        frag_load(sb, 1);
        compute();

        if (c + 2 < nch) {
            int nslot = slot + 2; if (nslot >= NSTAGE) nslot -= NSTAGE;
            load_stage(nslot, c + 2);
        }
        if (++slot == NSTAGE) slot = 0;
    }

    // Epilogue: m16n8k16 acc: c0,c1 -> (r, c),(r, c+1); c2,c3 -> (r+8, ..)
    const int er = lane >> 2, ec = (lane & 3) * 2;
    #pragma unroll
    for (int mt = 0; mt < 2; mt++) {
        const size_t row0 = bm + wm * 32 + mt * 16 + er;
        #pragma unroll
        for (int nt = 0; nt < 8; nt++) {
            const size_t col = bn + wn * 64 + nt * 8 + ec;
            if (EPI == 0) {
                float2 v0 = make_float2(acc[mt][nt][0], acc[mt][nt][1]);
                float2 v1 = make_float2(acc[mt][nt][2], acc[mt][nt][3]);
                *(float2*)&C[row0 * ldc + col]       = v0;
                *(float2*)&C[(row0 + 8) * ldc + col] = v1;
            } else {
                bf16 h0, l0, h1, l1;
                split2(acc[mt][nt][0], h0, l0); split2(acc[mt][nt][1], h1, l1);
                *(__nv_bfloat162*)&Ch[row0 * ldc + col] = __nv_bfloat162(h0, h1);
                *(__nv_bfloat162*)&Cl[row0 * ldc + col] = __nv_bfloat162(l0, l1);
                split2(acc[mt][nt][2], h0, l0); split2(acc[mt][nt][3], h1, l1);
                *(__nv_bfloat162*)&Ch[(row0 + 8) * ldc + col] = __nv_bfloat162(h0, h1);
                *(__nv_bfloat162*)&Cl[(row0 + 8) * ldc + col] = __nv_bfloat162(l0, l1);
            }
        }
    }
}

// ---------------------------------------------------------------------------
// Merged prep kernel (R10): one launch does
//   blocks [0, NCONV)          : x fp32 -> Xh/Xl bf16 (float4 per thread)
//   blocks [NCONV, NCONV+768)  : W{q,k,v} -> W^T hi/lo (32x32 tile transpose)
// ---------------------------------------------------------------------------
#define NCONV ((TOK * DIM) / 1024)     // 8192 conversion blocks

__global__ __launch_bounds__(256)
void prep_all(const float4* __restrict__ x4, uint2* __restrict__ oh, uint2* __restrict__ ol,
              const float* __restrict__ Wq, const float* __restrict__ Wk,
              const float* __restrict__ Wv, bf16* __restrict__ WTh, bf16* __restrict__ WTl)
{
    const int b = blockIdx.x;
    if (b < NCONV) {
        const size_t i = (size_t)b * 256 + threadIdx.x;
        float4 v = x4[i];
        bf16 h[4], l[4];
        split2(v.x, h[0], l[0]); split2(v.y, h[1], l[1]);
        split2(v.z, h[2], l[2]); split2(v.w, h[3], l[3]);
        oh[i] = *(uint2*)h;  ol[i] = *(uint2*)l;
        return;
    }
    // wtrans part
    __shared__ float t[32][33];
    const int widx = b - NCONV;         // 0..767
    const int w    = widx >> 8;         // 0,1,2 -> Wq,Wk,Wv
    const int r    = widx & 255;
    const int bx = (r & 15) * 32, by = (r >> 4) * 32;
    const float* W = (w == 0) ? Wq : (w == 1) ? Wk : Wv;
    bf16* Th = WTh + (size_t)w * DIM * DIM;
    bf16* Tl = WTl + (size_t)w * DIM * DIM;
    const int tx = threadIdx.x & 31, ty = threadIdx.x >> 5;
    #pragma unroll
    for (int i = ty; i < 32; i += 8)
        t[i][tx] = W[(size_t)(by + i) * DIM + bx + tx];
    __syncthreads();
    #pragma unroll
    for (int i = ty; i < 32; i += 8) {
        float v = t[tx][i];                               // = W[by+tx][bx+i]
        bf16 h, l; split2(v, h, l);
        Th[(size_t)(bx + i) * DIM + by + tx] = h;         // W^T
        Tl[(size_t)(bx + i) * DIM + by + tx] = l;
    }
}

// ---------------------------------------------------------------------------
// Row softmax of P (fp32) -> hi/lo bf16. One block per row (2048 cols).
// ---------------------------------------------------------------------------
__global__ __launch_bounds__(256)
void softmax_split(const float* __restrict__ P, bf16* __restrict__ Ph, bf16* __restrict__ Pl)
{
    const float* p = P + (size_t)blockIdx.x * SEQ;
    const int tid = threadIdx.x;
    __shared__ float red[8];

    float4 a = *(const float4*)&p[tid * 4];
    float4 b = *(const float4*)&p[1024 + tid * 4];
    float v[8] = {a.x, a.y, a.z, a.w, b.x, b.y, b.z, b.w};

    float m = v[0];
    #pragma unroll
    for (int i = 1; i < 8; i++) m = fmaxf(m, v[i]);
    #pragma unroll
    for (int o = 16; o > 0; o >>= 1) m = fmaxf(m, __shfl_xor_sync(~0u, m, o));
    if ((tid & 31) == 0) red[tid >> 5] = m;
    __syncthreads();
    m = red[0];
    #pragma unroll
    for (int i = 1; i < 8; i++) m = fmaxf(m, red[i]);
    __syncthreads();

    const float sc = 0.044194173824159216f;   // 1/sqrt(512)
    float s = 0.0f;
    #pragma unroll
    for (int i = 0; i < 8; i++) { v[i] = __expf((v[i] - m) * sc); s += v[i]; }
    #pragma unroll
    for (int o = 16; o > 0; o >>= 1) s += __shfl_xor_sync(~0u, s, o);
    if ((tid & 31) == 0) red[tid >> 5] = s;
    __syncthreads();
    s = 0.0f;
    #pragma unroll
    for (int i = 0; i < 8; i++) s += red[i];
    const float rinv = 1.0f / s;

    bf16 h[8], l[8];
    #pragma unroll
    for (int i = 0; i < 8; i++) split2(v[i] * rinv, h[i], l[i]);
    const size_t base = (size_t)blockIdx.x * SEQ;
    *(uint2*)&Ph[base + tid * 4]        = *(uint2*)&h[0];
    *(uint2*)&Ph[base + 1024 + tid * 4] = *(uint2*)&h[4];
    *(uint2*)&Pl[base + tid * 4]        = *(uint2*)&l[0];
    *(uint2*)&Pl[base + 1024 + tid * 4] = *(uint2*)&l[4];
}

// ---------------------------------------------------------------------------
extern "C" void kernel_launch(void* const* d_in, const int* in_sizes, int n_in,
                              void* d_out, int out_size)
{
    const float* x  = (const float*)d_in[0];
    const float* Wq = (const float*)d_in[1];
    const float* Wk = (const float*)d_in[2];
    const float* Wv = (const float*)d_in[3];
    float* out = (float*)d_out;

    bf16 *Xh, *Xl, *WTh, *WTl, *QKh, *QKl, *Vth, *Vtl, *Ph, *Pl;
    float* P;
    cudaGetSymbolAddress((void**)&Xh, g_Xh);   cudaGetSymbolAddress((void**)&Xl, g_Xl);
    cudaGetSymbolAddress((void**)&WTh, g_WTh); cudaGetSymbolAddress((void**)&WTl, g_WTl);
    cudaGetSymbolAddress((void**)&QKh, g_QKh); cudaGetSymbolAddress((void**)&QKl, g_QKl);
    cudaGetSymbolAddress((void**)&Vth, g_Vth); cudaGetSymbolAddress((void**)&Vtl, g_Vtl);
    cudaGetSymbolAddress((void**)&P, g_P);
    cudaGetSymbolAddress((void**)&Ph, g_Ph);   cudaGetSymbolAddress((void**)&Pl, g_Pl);

    const size_t QK = (size_t)TOK * DIM;

    cudaFuncSetAttribute(gemm_mma<0>, cudaFuncAttributeMaxDynamicSharedMemorySize, SMEM_BYTES);
    cudaFuncSetAttribute(gemm_mma<1>, cudaFuncAttributeMaxDynamicSharedMemorySize, SMEM_BYTES);

    // launch 1: all conversions (x split + 3 weight transposes)
    prep_all<<<NCONV + 768, 256>>>((const float4*)x, (uint2*)Xh, (uint2*)Xl,
                                   Wq, Wk, Wv, WTh, WTl);

    // launch 2: Q and K projections (z=0 -> Q via Wq, z=1 -> K via Wk)
    gemm_mma<1><<<dim3(4, 128, 2), 256, SMEM_BYTES>>>(
        Xh, Xl, DIM, 0, WTh, WTl, DIM, (size_t)DIM * DIM,
        nullptr, QKh, QKl, DIM, QK, DIM);
    // launch 3: V^T[e, tok] = sum_d Wv^T[e,d] * X[tok,d]
    gemm_mma<1><<<dim3(128, 4, 1), 256, SMEM_BYTES>>>(
        WTh + 2 * DIM * DIM, WTl + 2 * DIM * DIM, DIM, 0, Xh, Xl, DIM, 0,
        nullptr, Vth, Vtl, TOK, 0, DIM);

    // launch 4: P[b] = Q[b] @ K[b]^T  (fp32 out — R6 config; bf16 scores regressed)
    gemm_mma<0><<<dim3(16, 16, BATCH), 256, SMEM_BYTES>>>(
        QKh, QKl, DIM, (size_t)SEQ * DIM, QKh + QK, QKl + QK, DIM, (size_t)SEQ * DIM,
        P, nullptr, nullptr, SEQ, (size_t)SEQ * SEQ, DIM);

    // launch 5: softmax rows + split to bf16 hi/lo
    softmax_split<<<BATCH * SEQ, 256>>>(P, Ph, Pl);

    // launch 6: out[b] = P[b] @ V[b]  via B = V^T (ldb = TOK, batch column offset)
    gemm_mma<0><<<dim3(4, 16, BATCH), 256, SMEM_BYTES>>>(
        Ph, Pl, SEQ, (size_t)SEQ * SEQ, Vth, Vtl, TOK, (size_t)SEQ,
        out, nullptr, nullptr, DIM, (size_t)SEQ * DIM, SEQ);
}

// round 11
// speedup vs baseline: 1.5123x; 1.4032x over previous
#include <cuda_runtime.h>
#include <cuda_fp16.h>
#include <cstdint>

#define BATCH 8
#define SEQ   2048
#define DIM   512
#define TOK   (BATCH*SEQ)          // 16384

typedef __half fp16;

// ---------------------------------------------------------------------------
// Scratch (__device__ globals: allocation-guard safe)
// ---------------------------------------------------------------------------
__device__ fp16  g_Xh[(size_t)TOK * DIM],  g_Xl[(size_t)TOK * DIM];
__device__ fp16  g_WTh[3][DIM * DIM],      g_WTl[3][DIM * DIM];   // W^T hi/lo
__device__ fp16  g_QKh[2][(size_t)TOK * DIM], g_QKl[2][(size_t)TOK * DIM]; // Q=0, K=1
__device__ fp16  g_Vth[(size_t)DIM * TOK], g_Vtl[(size_t)DIM * TOK]; // V^T [512,16384]
__device__ float g_P [(size_t)BATCH * SEQ * SEQ];
__device__ fp16  g_Ph[(size_t)BATCH * SEQ * SEQ], g_Pl[(size_t)BATCH * SEQ * SEQ];

// ---------------------------------------------------------------------------
// Baseline-PTX helpers (sm_80+: valid for compute_103 target)
// ---------------------------------------------------------------------------
__device__ __forceinline__ uint32_t s2u(const void* p) {
    uint32_t a;
    asm("{ .reg .u64 t; cvta.to.shared.u64 t, %1; cvt.u32.u64 %0, t; }" : "=r"(a) : "l"(p));
    return a;
}
__device__ __forceinline__ void cp16(uint32_t saddr, const fp16* g) {
    asm volatile("cp.async.cg.shared.global [%0], [%1], 16;"
                 :: "r"(saddr), "l"(__cvta_generic_to_global(g)) : "memory");
}
__device__ __forceinline__ void cp_commit() {
    asm volatile("cp.async.commit_group;" ::: "memory");
}
template <int N>
__device__ __forceinline__ void cp_wait() {
    asm volatile("cp.async.wait_group %0;" :: "n"(N) : "memory");
}
__device__ __forceinline__ void ldsm4(uint32_t* d, uint32_t a) {
    asm volatile("ldmatrix.sync.aligned.m8n8.x4.shared.b16 {%0,%1,%2,%3}, [%4];"
                 : "=r"(d[0]), "=r"(d[1]), "=r"(d[2]), "=r"(d[3]) : "r"(a));
}
__device__ __forceinline__ void mma16816(float* c, const uint32_t* a, const uint32_t* b) {
    asm volatile("mma.sync.aligned.m16n8k16.row.col.f32.f16.f16.f32 "
                 "{%0,%1,%2,%3}, {%4,%5,%6,%7}, {%8,%9}, {%0,%1,%2,%3};"
                 : "+f"(c[0]), "+f"(c[1]), "+f"(c[2]), "+f"(c[3])
                 : "r"(a[0]), "r"(a[1]), "r"(a[2]), "r"(a[3]), "r"(b[0]), "r"(b[1]));
}
__device__ __forceinline__ void split2(float v, fp16& h, fp16& l) {
    h = __float2half_rn(v);
    l = __float2half_rn(v - __half2float(h));
}

// ---------------------------------------------------------------------------
// HMMA fp16 2-pass GEMM: C[M,N] = Ah·Bh^T + Al·Bh^T  (all operands K-major)
// A is hi/lo split (exact), B single fp16 (its truncation = the only error).
// CTA 128x128, BK=32, 256 threads (8 warps 4x2, warp tile 32x64), 3-stage
// cp.async pipeline, 2 CTAs/SM. R6 loop structure (load_stage AFTER compute).
// EPI=0: fp32 C. EPI=1: fp16 hi/lo Ch/Cl.  grid = (N/128, M/128, batch)
// ---------------------------------------------------------------------------
#define STAGE_BYTES 24576          // 3 tiles x 8KB (Ah, Al, Bh), 128 rows x 64B
#define NSTAGE      3
#define SMEM_BYTES  (NSTAGE * STAGE_BYTES)

template <int EPI>
__global__ __launch_bounds__(256, 2)
void gemm_mma(const fp16* __restrict__ Ah, const fp16* __restrict__ Al, int lda, size_t sA,
              const fp16* __restrict__ Bh, int ldb, size_t sB,
              float* __restrict__ C, fp16* __restrict__ Ch, fp16* __restrict__ Cl,
              int ldc, size_t sC, int Kd)
{
    extern __shared__ __align__(1024) char smem[];
    const uint32_t sbase = s2u(smem);

    const int tid  = threadIdx.x;
    const int lane = tid & 31;
    const int wid  = tid >> 5;
    const int wm   = wid >> 1;        // 0..3 -> m offset wm*32
    const int wn   = wid & 1;         // 0..1 -> n offset wn*64

    Ah += (size_t)blockIdx.z * sA;  Al += (size_t)blockIdx.z * sA;
    Bh += (size_t)blockIdx.z * sB;
    if (C)  C  += (size_t)blockIdx.z * sC;
    if (Ch) Ch += (size_t)blockIdx.z * sC;
    if (Cl) Cl += (size_t)blockIdx.z * sC;
    const size_t bm = (size_t)blockIdx.y * 128;
    const size_t bn = (size_t)blockIdx.x * 128;

    const int nch = Kd >> 5;          // chunks of 32

    // gmem->smem copy: per tile 512 chunks of 16B; thread handles rows r0, r0+64
    // at chunk ch.  Swizzle: xch = ch ^ ((row>>1)&3); (row+64) keeps same xch.
    const int cr0 = tid >> 2;          // 0..63
    const int cch = tid & 3;
    const uint32_t s0 = (uint32_t)cr0 * 64 + (uint32_t)((cch ^ ((cr0 >> 1) & 3)) << 4);

    auto load_stage = [&](int stage, int c) {
        const uint32_t so = sbase + (uint32_t)stage * STAGE_BYTES;
        const size_t ka = (size_t)(c << 5) + cch * 8;
        const fp16* a_h = Ah + (bm + cr0) * (size_t)lda + ka;
        const fp16* a_l = Al + (bm + cr0) * (size_t)lda + ka;
        const fp16* b_h = Bh + (bn + cr0) * (size_t)ldb + ka;
        const size_t r64a = (size_t)64 * lda, r64b = (size_t)64 * ldb;
        cp16(so +          s0,         a_h);
        cp16(so +          s0 + 4096u, a_h + r64a);
        cp16(so +  8192u + s0,         a_l);
        cp16(so +  8192u + s0 + 4096u, a_l + r64a);
        cp16(so + 16384u + s0,         b_h);
        cp16(so + 16384u + s0 + 4096u, b_h + r64b);
        cp_commit();
    };

    // ldmatrix per-lane pieces
    const int lg = lane >> 3, lr = lane & 7;
    const int a_row_off = (lg & 1) * 8 + lr;   // A-op (m-major)
    const int a_ch_off  = lg >> 1;
    const int b_row_off = (lg >> 1) * 8 + lr;  // B-op (n-major)
    const int b_ch_off  = lg & 1;

    uint32_t ahf[2][4], alf[2][4], bhf[4][4];

    auto frag_load = [&](uint32_t sb, int ks) {
        #pragma unroll
        for (int mt = 0; mt < 2; mt++) {
            const int row = wm * 32 + mt * 16 + a_row_off;
            const int ch  = 2 * ks + a_ch_off;
            const uint32_t off = (uint32_t)row * 64 + (uint32_t)(((ch ^ ((row >> 1) & 3)) & 3) << 4);
            ldsm4(ahf[mt], sb + off);
            ldsm4(alf[mt], sb + 8192u + off);
        }
        #pragma unroll
        for (int p = 0; p < 4; p++) {
            const int row = wn * 64 + p * 16 + b_row_off;
            const int ch  = 2 * ks + b_ch_off;
            const uint32_t off = (uint32_t)row * 64 + (uint32_t)(((ch ^ ((row >> 1) & 3)) & 3) << 4);
            ldsm4(bhf[p], sb + 16384u + off);
        }
    };

    float acc[2][8][4];
    #pragma unroll
    for (int mt = 0; mt < 2; mt++)
        #pragma unroll
        for (int nt = 0; nt < 8; nt++)
            #pragma unroll
            for (int q = 0; q < 4; q++) acc[mt][nt][q] = 0.0f;

    auto compute = [&]() {
        #pragma unroll
        for (int mt = 0; mt < 2; mt++)
            #pragma unroll
            for (int p = 0; p < 4; p++) {
                mma16816(acc[mt][2 * p],     ahf[mt], &bhf[p][0]);
                mma16816(acc[mt][2 * p + 1], ahf[mt], &bhf[p][2]);
            }
        #pragma unroll
        for (int mt = 0; mt < 2; mt++)
            #pragma unroll
            for (int p = 0; p < 4; p++) {
                mma16816(acc[mt][2 * p],     alf[mt], &bhf[p][0]);
                mma16816(acc[mt][2 * p + 1], alf[mt], &bhf[p][2]);
            }
    };

    // 3-stage pipeline prologue: stages 0,1 in flight
    load_stage(0, 0);
    load_stage(1, 1);

    int slot = 0;
    for (int c = 0; c < nch; c++) {
        if (c + 1 < nch) cp_wait<1>(); else cp_wait<0>();
        __syncthreads();

        const uint32_t sb = sbase + (uint32_t)slot * STAGE_BYTES;
        frag_load(sb, 0);
        compute();
        frag_load(sb, 1);
        compute();

        if (c + 2 < nch) {
            int nslot = slot + 2; if (nslot >= NSTAGE) nslot -= NSTAGE;
            load_stage(nslot, c + 2);
        }
        if (++slot == NSTAGE) slot = 0;
    }

    // Epilogue: m16n8k16 acc: c0,c1 -> (r, c),(r, c+1); c2,c3 -> (r+8, ..)
    const int er = lane >> 2, ec = (lane & 3) * 2;
    #pragma unroll
    for (int mt = 0; mt < 2; mt++) {
        const size_t row0 = bm + wm * 32 + mt * 16 + er;
        #pragma unroll
        for (int nt = 0; nt < 8; nt++) {
            const size_t col = bn + wn * 64 + nt * 8 + ec;
            if (EPI == 0) {
                float2 v0 = make_float2(acc[mt][nt][0], acc[mt][nt][1]);
                float2 v1 = make_float2(acc[mt][nt][2], acc[mt][nt][3]);
                *(float2*)&C[row0 * ldc + col]       = v0;
                *(float2*)&C[(row0 + 8) * ldc + col] = v1;
            } else {
                fp16 h0, l0, h1, l1;
                split2(acc[mt][nt][0], h0, l0); split2(acc[mt][nt][1], h1, l1);
                *(__half2*)&Ch[row0 * ldc + col] = __halves2half2(h0, h1);
                *(__half2*)&Cl[row0 * ldc + col] = __halves2half2(l0, l1);
                split2(acc[mt][nt][2], h0, l0); split2(acc[mt][nt][3], h1, l1);
                *(__half2*)&Ch[(row0 + 8) * ldc + col] = __halves2half2(h0, h1);
                *(__half2*)&Cl[(row0 + 8) * ldc + col] = __halves2half2(l0, l1);
            }
        }
    }
}

// ---------------------------------------------------------------------------
// Merged prep kernel: one launch does
//   blocks [0, NCONV)          : x fp32 -> Xh/Xl fp16 (float4 per thread)
//   blocks [NCONV, NCONV+768)  : W{q,k,v} -> W^T hi/lo fp16 (32x32 transpose)
// ---------------------------------------------------------------------------
#define NCONV ((TOK * DIM) / 1024)     // 8192 conversion blocks

__global__ __launch_bounds__(256)
void prep_all(const float4* __restrict__ x4, uint2* __restrict__ oh, uint2* __restrict__ ol,
              const float* __restrict__ Wq, const float* __restrict__ Wk,
              const float* __restrict__ Wv, fp16* __restrict__ WTh, fp16* __restrict__ WTl)
{
    const int b = blockIdx.x;
    if (b < NCONV) {
        const size_t i = (size_t)b * 256 + threadIdx.x;
        float4 v = x4[i];
        fp16 h[4], l[4];
        split2(v.x, h[0], l[0]); split2(v.y, h[1], l[1]);
        split2(v.z, h[2], l[2]); split2(v.w, h[3], l[3]);
        oh[i] = *(uint2*)h;  ol[i] = *(uint2*)l;
        return;
    }
    // wtrans part
    __shared__ float t[32][33];
    const int widx = b - NCONV;         // 0..767
    const int w    = widx >> 8;         // 0,1,2 -> Wq,Wk,Wv
    const int r    = widx & 255;
    const int bx = (r & 15) * 32, by = (r >> 4) * 32;
    const float* W = (w == 0) ? Wq : (w == 1) ? Wk : Wv;
    fp16* Th = WTh + (size_t)w * DIM * DIM;
    fp16* Tl = WTl + (size_t)w * DIM * DIM;
    const int tx = threadIdx.x & 31, ty = threadIdx.x >> 5;
    #pragma unroll
    for (int i = ty; i < 32; i += 8)
        t[i][tx] = W[(size_t)(by + i) * DIM + bx + tx];
    __syncthreads();
    #pragma unroll
    for (int i = ty; i < 32; i += 8) {
        float v = t[tx][i];                               // = W[by+tx][bx+i]
        fp16 h, l; split2(v, h, l);
        Th[(size_t)(bx + i) * DIM + by + tx] = h;         // W^T
        Tl[(size_t)(bx + i) * DIM + by + tx] = l;
    }
}

// ---------------------------------------------------------------------------
// Row softmax of P (fp32) -> hi/lo fp16. One block per row (2048 cols).
// ---------------------------------------------------------------------------
__global__ __launch_bounds__(256)
void softmax_split(const float* __restrict__ P, fp16* __restrict__ Ph, fp16* __restrict__ Pl)
{
    const float* p = P + (size_t)blockIdx.x * SEQ;
    const int tid = threadIdx.x;
    __shared__ float red[8];

    float4 a = *(const float4*)&p[tid * 4];
    float4 b = *(const float4*)&p[1024 + tid * 4];
    float v[8] = {a.x, a.y, a.z, a.w, b.x, b.y, b.z, b.w};

    float m = v[0];
    #pragma unroll
    for (int i = 1; i < 8; i++) m = fmaxf(m, v[i]);
    #pragma unroll
    for (int o = 16; o > 0; o >>= 1) m = fmaxf(m, __shfl_xor_sync(~0u, m, o));
    if ((tid & 31) == 0) red[tid >> 5] = m;
    __syncthreads();
    m = red[0];
    #pragma unroll
    for (int i = 1; i < 8; i++) m = fmaxf(m, red[i]);
    __syncthreads();

    const float sc = 0.044194173824159216f;   // 1/sqrt(512)
    float s = 0.0f;
    #pragma unroll
    for (int i = 0; i < 8; i++) { v[i] = __expf((v[i] - m) * sc); s += v[i]; }
    #pragma unroll
    for (int o = 16; o > 0; o >>= 1) s += __shfl_xor_sync(~0u, s, o);
    if ((tid & 31) == 0) red[tid >> 5] = s;
    __syncthreads();
    s = 0.0f;
    #pragma unroll
    for (int i = 0; i < 8; i++) s += red[i];
    const float rinv = 1.0f / s;

    fp16 h[8], l[8];
    #pragma unroll
    for (int i = 0; i < 8; i++) split2(v[i] * rinv, h[i], l[i]);
    const size_t base = (size_t)blockIdx.x * SEQ;
    *(uint2*)&Ph[base + tid * 4]        = *(uint2*)&h[0];
    *(uint2*)&Ph[base + 1024 + tid * 4] = *(uint2*)&h[4];
    *(uint2*)&Pl[base + tid * 4]        = *(uint2*)&l[0];
    *(uint2*)&Pl[base + 1024 + tid * 4] = *(uint2*)&l[4];
}

// ---------------------------------------------------------------------------
extern "C" void kernel_launch(void* const* d_in, const int* in_sizes, int n_in,
                              void* d_out, int out_size)
{
    const float* x  = (const float*)d_in[0];
    const float* Wq = (const float*)d_in[1];
    const float* Wk = (const float*)d_in[2];
    const float* Wv = (const float*)d_in[3];
    float* out = (float*)d_out;

    fp16 *Xh, *Xl, *WTh, *WTl, *QKh, *QKl, *Vth, *Vtl, *Ph, *Pl;
    float* P;
    cudaGetSymbolAddress((void**)&Xh, g_Xh);   cudaGetSymbolAddress((void**)&Xl, g_Xl);
    cudaGetSymbolAddress((void**)&WTh, g_WTh); cudaGetSymbolAddress((void**)&WTl, g_WTl);
    cudaGetSymbolAddress((void**)&QKh, g_QKh); cudaGetSymbolAddress((void**)&QKl, g_QKl);
    cudaGetSymbolAddress((void**)&Vth, g_Vth); cudaGetSymbolAddress((void**)&Vtl, g_Vtl);
    cudaGetSymbolAddress((void**)&P, g_P);
    cudaGetSymbolAddress((void**)&Ph, g_Ph);   cudaGetSymbolAddress((void**)&Pl, g_Pl);

    const size_t QK = (size_t)TOK * DIM;

    cudaFuncSetAttribute(gemm_mma<0>, cudaFuncAttributeMaxDynamicSharedMemorySize, SMEM_BYTES);
    cudaFuncSetAttribute(gemm_mma<1>, cudaFuncAttributeMaxDynamicSharedMemorySize, SMEM_BYTES);

    // launch 1: all conversions (x split + 3 weight transposes, hi/lo fp16)
    prep_all<<<NCONV + 768, 256>>>((const float4*)x, (uint2*)Xh, (uint2*)Xl,
                                   Wq, Wk, Wv, WTh, WTl);

    // launch 2: Q,K projections (z=0 Wq, z=1 Wk). A = X split, B = W^T hi.
    gemm_mma<1><<<dim3(4, 128, 2), 256, SMEM_BYTES>>>(
        Xh, Xl, DIM, 0, WTh, DIM, (size_t)DIM * DIM,
        nullptr, QKh, QKl, DIM, QK, DIM);
    // launch 3: V^T = Wv^T @ X^T. A = Wv^T split, B = X hi.
    gemm_mma<1><<<dim3(128, 4, 1), 256, SMEM_BYTES>>>(
        WTh + 2 * DIM * DIM, WTl + 2 * DIM * DIM, DIM, 0, Xh, DIM, 0,
        nullptr, Vth, Vtl, TOK, 0, DIM);

    // launch 4: scores P[b] = Q[b] @ K[b]^T. A = Q split, B = K hi. fp32 out.
    gemm_mma<0><<<dim3(16, 16, BATCH), 256, SMEM_BYTES>>>(
        QKh, QKl, DIM, (size_t)SEQ * DIM, QKh + QK, DIM, (size_t)SEQ * DIM,
        P, nullptr, nullptr, SEQ, (size_t)SEQ * SEQ, DIM);

    // launch 5: softmax rows + split to fp16 hi/lo
    softmax_split<<<BATCH * SEQ, 256>>>(P, Ph, Pl);

    // launch 6: out[b] = P[b] @ V[b]. A = P split, B = V^T hi (ldb = TOK).
    gemm_mma<0><<<dim3(4, 16, BATCH), 256, SMEM_BYTES>>>(
        Ph, Pl, SEQ, (size_t)SEQ * SEQ, Vth, TOK, (size_t)SEQ,
        out, nullptr, nullptr, DIM, (size_t)SEQ * DIM, SEQ);
}

// round 12
// speedup vs baseline: 2.5011x; 1.6538x over previous
#include <cuda_runtime.h>
#include <cuda_fp16.h>
#include <cstdint>

#define BATCH 8
#define SEQ   2048
#define DIM   512
#define TOK   (BATCH*SEQ)          // 16384

typedef __half fp16;

// ---------------------------------------------------------------------------
// Scratch (__device__ globals: allocation-guard safe)
// ---------------------------------------------------------------------------
__device__ fp16  g_Xf[(size_t)TOK * DIM];
__device__ fp16  g_WT[3][DIM * DIM];                       // W^T fp16
__device__ fp16  g_QK[2][(size_t)TOK * DIM];               // Q=0, K=1
__device__ fp16  g_Vt[(size_t)DIM * TOK];                  // V^T [512,16384]
__device__ float g_P [(size_t)BATCH * SEQ * SEQ];
__device__ fp16  g_Pf[(size_t)BATCH * SEQ * SEQ];

// ---------------------------------------------------------------------------
// Baseline-PTX helpers (sm_80+: valid for compute_103 target)
// ---------------------------------------------------------------------------
__device__ __forceinline__ uint32_t s2u(const void* p) {
    uint32_t a;
    asm("{ .reg .u64 t; cvta.to.shared.u64 t, %1; cvt.u32.u64 %0, t; }" : "=r"(a) : "l"(p));
    return a;
}
__device__ __forceinline__ void cp16(uint32_t saddr, const fp16* g) {
    asm volatile("cp.async.cg.shared.global [%0], [%1], 16;"
                 :: "r"(saddr), "l"(__cvta_generic_to_global(g)) : "memory");
}
__device__ __forceinline__ void cp_commit() {
    asm volatile("cp.async.commit_group;" ::: "memory");
}
template <int N>
__device__ __forceinline__ void cp_wait() {
    asm volatile("cp.async.wait_group %0;" :: "n"(N) : "memory");
}
__device__ __forceinline__ void ldsm4(uint32_t* d, uint32_t a) {
    asm volatile("ldmatrix.sync.aligned.m8n8.x4.shared.b16 {%0,%1,%2,%3}, [%4];"
                 : "=r"(d[0]), "=r"(d[1]), "=r"(d[2]), "=r"(d[3]) : "r"(a));
}
__device__ __forceinline__ void mma16816(float* c, const uint32_t* a, const uint32_t* b) {
    asm volatile("mma.sync.aligned.m16n8k16.row.col.f32.f16.f16.f32 "
                 "{%0,%1,%2,%3}, {%4,%5,%6,%7}, {%8,%9}, {%0,%1,%2,%3};"
                 : "+f"(c[0]), "+f"(c[1]), "+f"(c[2]), "+f"(c[3])
                 : "r"(a[0]), "r"(a[1]), "r"(a[2]), "r"(a[3]), "r"(b[0]), "r"(b[1]));
}

// ---------------------------------------------------------------------------
// Single-pass fp16 GEMM: C[M,N] = A·B^T  (both operands K-major fp16)
// CTA 128x128, BK=32, 256 threads (8 warps 4x2, warp tile 32x64), 4-stage
// cp.async pipeline, 2 CTAs/SM. R6 loop structure (load_stage AFTER compute).
// EPI=0: fp32 C. EPI=1: fp16 C.  grid = (N/128, M/128, batch)
// ---------------------------------------------------------------------------
#define STAGE_BYTES 16384          // 2 tiles x 8KB (A, B), 128 rows x 64B
#define NSTAGE      4
#define SMEM_BYTES  (NSTAGE * STAGE_BYTES)

template <int EPI>
__global__ __launch_bounds__(256, 2)
void gemm_mma(const fp16* __restrict__ A, int lda, size_t sA,
              const fp16* __restrict__ B, int ldb, size_t sB,
              float* __restrict__ C, fp16* __restrict__ Cf,
              int ldc, size_t sC, int Kd)
{
    extern __shared__ __align__(1024) char smem[];
    const uint32_t sbase = s2u(smem);

    const int tid  = threadIdx.x;
    const int lane = tid & 31;
    const int wid  = tid >> 5;
    const int wm   = wid >> 1;        // 0..3 -> m offset wm*32
    const int wn   = wid & 1;         // 0..1 -> n offset wn*64

    A += (size_t)blockIdx.z * sA;
    B += (size_t)blockIdx.z * sB;
    if (C)  C  += (size_t)blockIdx.z * sC;
    if (Cf) Cf += (size_t)blockIdx.z * sC;
    const size_t bm = (size_t)blockIdx.y * 128;
    const size_t bn = (size_t)blockIdx.x * 128;

    const int nch = Kd >> 5;          // chunks of 32

    // gmem->smem: per tile 512 chunks of 16B; thread does rows cr0, cr0+64.
    // Swizzle: xch = ch ^ ((row>>1)&3).
    const int cr0 = tid >> 2;          // 0..63
    const int cch = tid & 3;
    const uint32_t s0 = (uint32_t)cr0 * 64 + (uint32_t)((cch ^ ((cr0 >> 1) & 3)) << 4);

    auto load_stage = [&](int stage, int c) {
        const uint32_t so = sbase + (uint32_t)stage * STAGE_BYTES;
        const size_t ka = (size_t)(c << 5) + cch * 8;
        const fp16* a_p = A + (bm + cr0) * (size_t)lda + ka;
        const fp16* b_p = B + (bn + cr0) * (size_t)ldb + ka;
        const size_t r64a = (size_t)64 * lda, r64b = (size_t)64 * ldb;
        cp16(so +         s0,         a_p);
        cp16(so +         s0 + 4096u, a_p + r64a);
        cp16(so + 8192u + s0,         b_p);
        cp16(so + 8192u + s0 + 4096u, b_p + r64b);
        cp_commit();
    };

    // ldmatrix per-lane pieces
    const int lg = lane >> 3, lr = lane & 7;
    const int a_row_off = (lg & 1) * 8 + lr;   // A-op (m-major)
    const int a_ch_off  = lg >> 1;
    const int b_row_off = (lg >> 1) * 8 + lr;  // B-op (n-major)
    const int b_ch_off  = lg & 1;

    uint32_t af[2][4], bf[4][4];

    auto frag_load = [&](uint32_t sb, int ks) {
        #pragma unroll
        for (int mt = 0; mt < 2; mt++) {
            const int row = wm * 32 + mt * 16 + a_row_off;
            const int ch  = 2 * ks + a_ch_off;
            const uint32_t off = (uint32_t)row * 64 + (uint32_t)(((ch ^ ((row >> 1) & 3)) & 3) << 4);
            ldsm4(af[mt], sb + off);
        }
        #pragma unroll
        for (int p = 0; p < 4; p++) {
            const int row = wn * 64 + p * 16 + b_row_off;
            const int ch  = 2 * ks + b_ch_off;
            const uint32_t off = (uint32_t)row * 64 + (uint32_t)(((ch ^ ((row >> 1) & 3)) & 3) << 4);
            ldsm4(bf[p], sb + 8192u + off);
        }
    };

    float acc[2][8][4];
    #pragma unroll
    for (int mt = 0; mt < 2; mt++)
        #pragma unroll
        for (int nt = 0; nt < 8; nt++)
            #pragma unroll
            for (int q = 0; q < 4; q++) acc[mt][nt][q] = 0.0f;

    auto compute = [&]() {
        #pragma unroll
        for (int mt = 0; mt < 2; mt++)
            #pragma unroll
            for (int p = 0; p < 4; p++) {
                mma16816(acc[mt][2 * p],     af[mt], &bf[p][0]);
                mma16816(acc[mt][2 * p + 1], af[mt], &bf[p][2]);
            }
    };

    // 4-stage pipeline prologue: stages 0,1,2 in flight
    load_stage(0, 0);
    load_stage(1, 1);
    if (nch > 2) load_stage(2, 2);

    int slot = 0;
    for (int c = 0; c < nch; c++) {
        if (c + 2 < nch)      cp_wait<2>();
        else if (c + 1 < nch) cp_wait<1>();
        else                  cp_wait<0>();
        __syncthreads();

        const uint32_t sb = sbase + (uint32_t)slot * STAGE_BYTES;
        frag_load(sb, 0);
        compute();
        frag_load(sb, 1);
        compute();

        if (c + 3 < nch) {
            int nslot = slot + 3; if (nslot >= NSTAGE) nslot -= NSTAGE;
            load_stage(nslot, c + 3);
        }
        if (++slot == NSTAGE) slot = 0;
    }

    // Epilogue: m16n8k16 acc: c0,c1 -> (r, c),(r, c+1); c2,c3 -> (r+8, ..)
    const int er = lane >> 2, ec = (lane & 3) * 2;
    #pragma unroll
    for (int mt = 0; mt < 2; mt++) {
        const size_t row0 = bm + wm * 32 + mt * 16 + er;
        #pragma unroll
        for (int nt = 0; nt < 8; nt++) {
            const size_t col = bn + wn * 64 + nt * 8 + ec;
            if (EPI == 0) {
                float2 v0 = make_float2(acc[mt][nt][0], acc[mt][nt][1]);
                float2 v1 = make_float2(acc[mt][nt][2], acc[mt][nt][3]);
                *(float2*)&C[row0 * ldc + col]       = v0;
                *(float2*)&C[(row0 + 8) * ldc + col] = v1;
            } else {
                *(__half2*)&Cf[row0 * ldc + col] =
                    __halves2half2(__float2half_rn(acc[mt][nt][0]), __float2half_rn(acc[mt][nt][1]));
                *(__half2*)&Cf[(row0 + 8) * ldc + col] =
                    __halves2half2(__float2half_rn(acc[mt][nt][2]), __float2half_rn(acc[mt][nt][3]));
            }
        }
    }
}

// ---------------------------------------------------------------------------
// Merged prep kernel: one launch does
//   blocks [0, NCONV)          : x fp32 -> Xf fp16 (float4 per thread)
//   blocks [NCONV, NCONV+768)  : W{q,k,v} -> W^T fp16 (32x32 transpose)
// ---------------------------------------------------------------------------
#define NCONV ((TOK * DIM) / 1024)     // 8192 conversion blocks

__global__ __launch_bounds__(256)
void prep_all(const float4* __restrict__ x4, uint2* __restrict__ of,
              const float* __restrict__ Wq, const float* __restrict__ Wk,
              const float* __restrict__ Wv, fp16* __restrict__ WT)
{
    const int b = blockIdx.x;
    if (b < NCONV) {
        const size_t i = (size_t)b * 256 + threadIdx.x;
        float4 v = x4[i];
        fp16 h[4] = {__float2half_rn(v.x), __float2half_rn(v.y),
                     __float2half_rn(v.z), __float2half_rn(v.w)};
        of[i] = *(uint2*)h;
        return;
    }
    // wtrans part
    __shared__ float t[32][33];
    const int widx = b - NCONV;         // 0..767
    const int w    = widx >> 8;         // 0,1,2 -> Wq,Wk,Wv
    const int r    = widx & 255;
    const int bx = (r & 15) * 32, by = (r >> 4) * 32;
    const float* W = (w == 0) ? Wq : (w == 1) ? Wk : Wv;
    fp16* T = WT + (size_t)w * DIM * DIM;
    const int tx = threadIdx.x & 31, ty = threadIdx.x >> 5;
    #pragma unroll
    for (int i = ty; i < 32; i += 8)
        t[i][tx] = W[(size_t)(by + i) * DIM + bx + tx];
    __syncthreads();
    #pragma unroll
    for (int i = ty; i < 32; i += 8)
        T[(size_t)(bx + i) * DIM + by + tx] = __float2half_rn(t[tx][i]);   // W^T
}

// ---------------------------------------------------------------------------
// Row softmax of P (fp32) -> fp16. One block per row (2048 cols).
// ---------------------------------------------------------------------------
__global__ __launch_bounds__(256)
void softmax_half(const float* __restrict__ P, fp16* __restrict__ Pf)
{
    const float* p = P + (size_t)blockIdx.x * SEQ;
    const int tid = threadIdx.x;
    __shared__ float red[8];

    float4 a = *(const float4*)&p[tid * 4];
    float4 b = *(const float4*)&p[1024 + tid * 4];
    float v[8] = {a.x, a.y, a.z, a.w, b.x, b.y, b.z, b.w};

    float m = v[0];
    #pragma unroll
    for (int i = 1; i < 8; i++) m = fmaxf(m, v[i]);
    #pragma unroll
    for (int o = 16; o > 0; o >>= 1) m = fmaxf(m, __shfl_xor_sync(~0u, m, o));
    if ((tid & 31) == 0) red[tid >> 5] = m;
    __syncthreads();
    m = red[0];
    #pragma unroll
    for (int i = 1; i < 8; i++) m = fmaxf(m, red[i]);
    __syncthreads();

    const float sc = 0.044194173824159216f;   // 1/sqrt(512)
    float s = 0.0f;
    #pragma unroll
    for (int i = 0; i < 8; i++) { v[i] = __expf((v[i] - m) * sc); s += v[i]; }
    #pragma unroll
    for (int o = 16; o > 0; o >>= 1) s += __shfl_xor_sync(~0u, s, o);
    if ((tid & 31) == 0) red[tid >> 5] = s;
    __syncthreads();
    s = 0.0f;
    #pragma unroll
    for (int i = 0; i < 8; i++) s += red[i];
    const float rinv = 1.0f / s;

    fp16 h[8];
    #pragma unroll
    for (int i = 0; i < 8; i++) h[i] = __float2half_rn(v[i] * rinv);
    const size_t base = (size_t)blockIdx.x * SEQ;
    *(uint2*)&Pf[base + tid * 4]        = *(uint2*)&h[0];
    *(uint2*)&Pf[base + 1024 + tid * 4] = *(uint2*)&h[4];
}

// ---------------------------------------------------------------------------
extern "C" void kernel_launch(void* const* d_in, const int* in_sizes, int n_in,
                              void* d_out, int out_size)
{
    const float* x  = (const float*)d_in[0];
    const float* Wq = (const float*)d_in[1];
    const float* Wk = (const float*)d_in[2];
    const float* Wv = (const float*)d_in[3];
    float* out = (float*)d_out;

    fp16 *Xf, *WT, *QK, *Vt, *Pf;
    float* P;
    cudaGetSymbolAddress((void**)&Xf, g_Xf);
    cudaGetSymbolAddress((void**)&WT, g_WT);
    cudaGetSymbolAddress((void**)&QK, g_QK);
    cudaGetSymbolAddress((void**)&Vt, g_Vt);
    cudaGetSymbolAddress((void**)&P, g_P);
    cudaGetSymbolAddress((void**)&Pf, g_Pf);

    const size_t QKs = (size_t)TOK * DIM;

    cudaFuncSetAttribute(gemm_mma<0>, cudaFuncAttributeMaxDynamicSharedMemorySize, SMEM_BYTES);
    cudaFuncSetAttribute(gemm_mma<1>, cudaFuncAttributeMaxDynamicSharedMemorySize, SMEM_BYTES);

    // launch 1: all conversions (x -> fp16, W -> W^T fp16)
    prep_all<<<NCONV + 768, 256>>>((const float4*)x, (uint2*)Xf, Wq, Wk, Wv, WT);

    // launch 2: Q,K projections (z=0 Wq, z=1 Wk). C fp16.
    gemm_mma<1><<<dim3(4, 128, 2), 256, SMEM_BYTES>>>(
        Xf, DIM, 0, WT, DIM, (size_t)DIM * DIM,
        nullptr, QK, DIM, QKs, DIM);
    // launch 3: V^T = Wv^T @ X^T. C fp16.
    gemm_mma<1><<<dim3(128, 4, 1), 256, SMEM_BYTES>>>(
        WT + 2 * DIM * DIM, DIM, 0, Xf, DIM, 0,
        nullptr, Vt, TOK, 0, DIM);

    // launch 4: scores P[b] = Q[b] @ K[b]^T. fp32 out.
    gemm_mma<0><<<dim3(16, 16, BATCH), 256, SMEM_BYTES>>>(
        QK, DIM, (size_t)SEQ * DIM, QK + QKs, DIM, (size_t)SEQ * DIM,
        P, nullptr, SEQ, (size_t)SEQ * SEQ, DIM);

    // launch 5: softmax rows -> fp16 probs
    softmax_half<<<BATCH * SEQ, 256>>>(P, Pf);

    // launch 6: out[b] = P[b] @ V[b] via B = V^T (ldb = TOK). fp32 out.
    gemm_mma<0><<<dim3(4, 16, BATCH), 256, SMEM_BYTES>>>(
        Pf, SEQ, (size_t)SEQ * SEQ, Vt, TOK, (size_t)SEQ,
        out, nullptr, DIM, (size_t)SEQ * DIM, SEQ);
}